// round 7
// baseline (speedup 1.0000x reference)
#include <cuda_runtime.h>

// ---------------- problem constants ----------------
#define SEQ   320
#define HH    400          // hidden size H
#define NG    1600         // 4*H gate width
#define BI2   800          // 2*H bilstm output width
#define WDIM  300
#define TDIM  100
#define INDIM 400

// LSTM distribution: 67 blocks per direction, 6 hidden units each (last block 4)
#define GSZ   67
#define KB    6

// ---------------- device scratch (no allocations allowed) ----------------
__device__ float d_x[SEQ * INDIM];        // embedded input
__device__ float d_g0[SEQ * NG];          // precomputed x@W_ih^T + biases (fwd)
__device__ float d_g1[SEQ * NG];          // (bwd)
__device__ float d_hv0[SEQ * BI2];        // layer-0 bilstm output
__device__ float d_hv1[SEQ * BI2];        // layer-1 bilstm output
__device__ float d_pa[SEQ * NG];          // a = hv@w1a^T + b1
__device__ float d_pb[SEQ * NG];          // b = hv@w1b^T
__device__ float d_hbuf[2][2][HH];        // [dir][parity][H] recurrent h exchange
__device__ int   d_hflag[2][GSZ];         // per-block publish flags (monotonic per launch)
__device__ int   d_done;                  // end-of-kernel reset barrier

// ---------------- math helpers ----------------
__device__ __forceinline__ float sigm_f(float x) {
    float e = __expf(-x);
    return 1.0f / (1.0f + e);
}
__device__ __forceinline__ float tanh_f(float x) {
    float e = __expf(2.0f * x);
    return 1.0f - 2.0f / (e + 1.0f);   // exact limits at +-inf
}

// ---------------- embedding concat ----------------
__global__ void embed_kernel(const int* __restrict__ words, const int* __restrict__ tags,
                             const float* __restrict__ wemb, const float* __restrict__ temb) {
    int idx = blockIdx.x * blockDim.x + threadIdx.x;
    if (idx >= SEQ * INDIM) return;
    int t = idx / INDIM, d = idx % INDIM;
    d_x[idx] = (d < WDIM) ? wemb[words[t] * WDIM + d]
                          : temb[tags[t] * TDIM + (d - WDIM)];
}

// ---------------- dual GEMM: z=0/1 select B/bias/C; C[M,N] = A*B^T + b0 + b1 ----
// M=320 (grid.y=5), N=1600 (grid.x=25), ldc = NG. K multiple of 16.
__global__ void __launch_bounds__(256) gemm_tn2(
    const float* __restrict__ A, int lda,
    const float* __restrict__ B0, const float* __restrict__ B1, int ldb,
    const float* __restrict__ b00, const float* __restrict__ b01,
    const float* __restrict__ b10, const float* __restrict__ b11,
    float* __restrict__ C0, float* __restrict__ C1, int K)
{
    const float* B     = blockIdx.z ? B1  : B0;
    const float* bias0 = blockIdx.z ? b10 : b00;
    const float* bias1 = blockIdx.z ? b11 : b01;
    float*       C     = blockIdx.z ? C1  : C0;

    __shared__ float As[16][68];
    __shared__ float Bs[16][68];
    int tid = threadIdx.x;
    int bm = blockIdx.y * 64, bn = blockIdx.x * 64;
    int row = tid >> 2, kq = tid & 3;      // loaders
    int ty  = tid >> 4, tx = tid & 15;     // compute 4x4 each
    float acc[4][4] = {};

    for (int k0 = 0; k0 < K; k0 += 16) {
        __syncthreads();
        float4 av = *(const float4*)&A[(bm + row) * lda + k0 + kq * 4];
        float4 bv = *(const float4*)&B[(bn + row) * ldb + k0 + kq * 4];
        As[kq*4+0][row] = av.x; As[kq*4+1][row] = av.y;
        As[kq*4+2][row] = av.z; As[kq*4+3][row] = av.w;
        Bs[kq*4+0][row] = bv.x; Bs[kq*4+1][row] = bv.y;
        Bs[kq*4+2][row] = bv.z; Bs[kq*4+3][row] = bv.w;
        __syncthreads();
        #pragma unroll
        for (int kk = 0; kk < 16; kk++) {
            float4 a4 = *(const float4*)&As[kk][ty * 4];
            float4 b4 = *(const float4*)&Bs[kk][tx * 4];
            float aa[4] = {a4.x, a4.y, a4.z, a4.w};
            float bb[4] = {b4.x, b4.y, b4.z, b4.w};
            #pragma unroll
            for (int i = 0; i < 4; i++)
                #pragma unroll
                for (int j = 0; j < 4; j++)
                    acc[i][j] += aa[i] * bb[j];
        }
    }
    #pragma unroll
    for (int i = 0; i < 4; i++) {
        int m = bm + ty * 4 + i;
        #pragma unroll
        for (int j = 0; j < 4; j++) {
            int n = bn + tx * 4 + j;
            float v = acc[i][j];
            if (bias0) v += bias0[n];
            if (bias1) v += bias1[n];
            C[m * NG + n] = v;
        }
    }
}

// ---------------- persistent bidirectional LSTM phase ----------------
// grid = 2*GSZ blocks, 256 threads. blocks [0,GSZ): forward, [GSZ,2*GSZ): backward.
// Each block owns KB hidden units: its 4*KB W_hh rows stay resident in smem.
// Per-step sync: each block publishes a per-block flag (fence + STG); consumers
// poll all GSZ flags in parallel (threads 0..GSZ-1, volatile L2 loads).
// NO per-step atomics. One contended atomic barrier at kernel end resets flags.
__global__ void __launch_bounds__(256, 1) lstm_phase(
    const float* __restrict__ whh_f, const float* __restrict__ whh_b,
    const float* __restrict__ h0, const float* __restrict__ c0, int h0base,
    const float* __restrict__ gpre_f, const float* __restrict__ gpre_b,
    float* __restrict__ hv_out)
{
    __shared__ float Ws[4 * KB][HH];     // 38.4 KB
    __shared__ float h_s[HH];
    __shared__ float g_s[4 * KB];
    __shared__ float gp_s[4 * KB];
    __shared__ float c_s[KB];

    const int tid  = threadIdx.x;
    const int dir  = (blockIdx.x >= GSZ) ? 1 : 0;
    const int slot = dir ? (blockIdx.x - GSZ) : blockIdx.x;
    const int k0   = slot * KB;
    const int kn   = min(KB, HH - k0);   // last block covers 4
    const float* whh  = dir ? whh_b  : whh_f;
    const float* gpre = dir ? gpre_b : gpre_f;
    const int h0row = h0base + dir;

    // preload W_hh slice: smem row r = gate*KB + kk  <->  W_hh row gate*HH + k0 + kk
    for (int idx = tid; idx < 4 * KB * HH; idx += blockDim.x) {
        int r = idx / HH, m = idx - r * HH;
        int g = r / KB, kk = r - g * KB;
        Ws[r][m] = (kk < kn) ? whh[(g * HH + k0 + kk) * HH + m] : 0.0f;
    }
    if (tid < KB) c_s[tid] = (tid < kn) ? c0[h0row * HH + k0 + tid] : 0.0f;
    __syncthreads();

    const int wid = tid >> 5, lane = tid & 31;
    volatile int* myflag = &d_hflag[dir][slot];
    volatile int* pollfl = (tid < GSZ) ? &d_hflag[dir][tid] : 0;

    for (int s = 0; s < SEQ; s++) {
        const int t = dir ? (SEQ - 1 - s) : s;   // physical time index

        // prefetch this step's precomputed gate inputs (independent of h)
        if (tid < 4 * KB) {
            int g = tid / KB, kk = tid - g * KB;
            gp_s[tid] = (kk < kn) ? __ldg(&gpre[t * NG + g * HH + k0 + kk]) : 0.0f;
        }
        // wait: all blocks of this direction must have published h(s-1)
        if (s > 0 && tid < GSZ) {
            while (*pollfl < s) { }
        }
        __syncthreads();

        // load h (L2-coherent, bypass L1)
        if (s == 0) {
            for (int m = tid; m < HH; m += blockDim.x) h_s[m] = h0[h0row * HH + m];
        } else {
            const float* hsrc = d_hbuf[dir][s & 1];
            for (int m = tid; m < HH; m += blockDim.x) h_s[m] = __ldcg(&hsrc[m]);
        }
        __syncthreads();

        // 24 dot products of length 400; warp w handles rows w, w+8, w+16
        {
            const float* w0  = Ws[wid];
            const float* w1  = Ws[wid + 8];
            const float* w2p = Ws[wid + 16];
            float s0 = 0.f, s1 = 0.f, s2 = 0.f;
            #pragma unroll
            for (int u = 0; u < 12; u++) {
                int m = lane + u * 32;
                float hv = h_s[m];
                s0 += w0[m] * hv; s1 += w1[m] * hv; s2 += w2p[m] * hv;
            }
            {   // tail: elements 384..399 (lanes 0..15)
                int m = lane + 384;
                if (m < HH) {
                    float hv = h_s[m];
                    s0 += w0[m] * hv; s1 += w1[m] * hv; s2 += w2p[m] * hv;
                }
            }
            #pragma unroll
            for (int off = 16; off; off >>= 1) {
                s0 += __shfl_xor_sync(0xffffffffu, s0, off);
                s1 += __shfl_xor_sync(0xffffffffu, s1, off);
                s2 += __shfl_xor_sync(0xffffffffu, s2, off);
            }
            if (lane == 0) {
                g_s[wid]      = s0 + gp_s[wid];
                g_s[wid + 8]  = s1 + gp_s[wid + 8];
                g_s[wid + 16] = s2 + gp_s[wid + 16];
            }
        }
        __syncthreads();

        // gate nonlinearities + state update (warp 0 only: tid < kn <= 6)
        if (tid < kn) {
            float gi = g_s[0 * KB + tid];
            float gf = g_s[1 * KB + tid];
            float gg = g_s[2 * KB + tid];
            float go = g_s[3 * KB + tid];
            float i = sigm_f(gi), f = sigm_f(gf), o = sigm_f(go);
            float c = f * c_s[tid] + i * tanh_f(gg);
            c_s[tid] = c;
            float h = o * tanh_f(c);
            d_hbuf[dir][(s + 1) & 1][k0 + tid] = h;
            hv_out[t * BI2 + dir * HH + k0 + tid] = h;
        }
        // publish: h writers are lanes 0..kn-1 of warp 0; lane 0 fences+flags
        __syncwarp();
        if (tid == 0 && s < SEQ - 1) {
            __threadfence();
            *myflag = s + 1;
        }
        // warps 1..7 proceed; they re-converge at the next __syncthreads
    }

    // end-of-kernel barrier: last block resets flags for the next launch/replay
    __syncthreads();
    if (tid == 0) {
        __threadfence();
        int v = atomicAdd(&d_done, 1) + 1;
        if (v == 2 * GSZ) {
            #pragma unroll
            for (int i = 0; i < 2 * GSZ; i++) ((int*)d_hflag)[i] = 0;
            __threadfence();
            d_done = 0;
        }
    }
}

// ---------------- output border init ----------------
__global__ void init_out(float* __restrict__ out) {
    int i = blockIdx.x * blockDim.x + threadIdx.x;
    if (i <= SEQ) {
        out[i]       = (i == 0) ? 1.0f : 0.0f;   // row 0
        out[i * 321] = (i == 0) ? 1.0f : 0.0f;   // col 0
    }
}

// ---------------- pairwise biaffine-style scores ----------------
// out[1+i][1+j] = (i==j) ? 0 : sum_k relu(a[i,k]+b[j,k])*w2[k] + b2
__global__ void __launch_bounds__(256) pairwise_kernel(
    const float* __restrict__ A, const float* __restrict__ Bm,
    const float* __restrict__ w2, const float* __restrict__ b2,
    float* __restrict__ out)
{
    __shared__ float As[32][34], Bs[32][34], w2s[32];
    int tid = threadIdx.x;
    int bi = blockIdx.y * 32, bj = blockIdx.x * 32;
    int ty = tid >> 4, tx = tid & 15;
    int row = tid >> 3, kq = tid & 7;
    float a00 = 0.f, a01 = 0.f, a10 = 0.f, a11 = 0.f;

    for (int k0 = 0; k0 < NG; k0 += 32) {
        __syncthreads();
        float4 av = *(const float4*)&A [(bi + row) * NG + k0 + kq * 4];
        float4 bv = *(const float4*)&Bm[(bj + row) * NG + k0 + kq * 4];
        As[kq*4+0][row] = av.x; As[kq*4+1][row] = av.y;
        As[kq*4+2][row] = av.z; As[kq*4+3][row] = av.w;
        Bs[kq*4+0][row] = bv.x; Bs[kq*4+1][row] = bv.y;
        Bs[kq*4+2][row] = bv.z; Bs[kq*4+3][row] = bv.w;
        if (tid < 32) w2s[tid] = w2[k0 + tid];
        __syncthreads();
        #pragma unroll
        for (int kk = 0; kk < 32; kk++) {
            float w = w2s[kk];
            float2 a = *(const float2*)&As[kk][ty * 2];
            float2 b = *(const float2*)&Bs[kk][tx * 2];
            a00 += fmaxf(a.x + b.x, 0.f) * w;
            a01 += fmaxf(a.x + b.y, 0.f) * w;
            a10 += fmaxf(a.y + b.x, 0.f) * w;
            a11 += fmaxf(a.y + b.y, 0.f) * w;
        }
    }
    float bb = b2[0];
    int gi = bi + ty * 2, gj = bj + tx * 2;
    out[(gi + 1) * 321 + (gj + 1)] = (gi     == gj    ) ? 0.f : a00 + bb;
    out[(gi + 1) * 321 + (gj + 2)] = (gi     == gj + 1) ? 0.f : a01 + bb;
    out[(gi + 2) * 321 + (gj + 1)] = (gi + 1 == gj    ) ? 0.f : a10 + bb;
    out[(gi + 2) * 321 + (gj + 2)] = (gi     == gj    ) ? 0.f : a11 + bb;
}

// ---------------- host orchestration ----------------
extern "C" void kernel_launch(void* const* d_in, const int* in_sizes, int n_in,
                              void* d_out, int out_size) {
    const int*   words    = (const int*)  d_in[0];
    const int*   tags     = (const int*)  d_in[1];
    const float* wemb     = (const float*)d_in[3];
    const float* temb     = (const float*)d_in[4];
    const float* h0       = (const float*)d_in[5];
    const float* c0       = (const float*)d_in[6];
    const float* w_ih_l0  = (const float*)d_in[7];
    const float* w_hh_l0  = (const float*)d_in[8];
    const float* b_ih_l0  = (const float*)d_in[9];
    const float* b_hh_l0  = (const float*)d_in[10];
    const float* w_ih_l0r = (const float*)d_in[11];
    const float* w_hh_l0r = (const float*)d_in[12];
    const float* b_ih_l0r = (const float*)d_in[13];
    const float* b_hh_l0r = (const float*)d_in[14];
    const float* w_ih_l1  = (const float*)d_in[15];
    const float* w_hh_l1  = (const float*)d_in[16];
    const float* b_ih_l1  = (const float*)d_in[17];
    const float* b_hh_l1  = (const float*)d_in[18];
    const float* w_ih_l1r = (const float*)d_in[19];
    const float* w_hh_l1r = (const float*)d_in[20];
    const float* b_ih_l1r = (const float*)d_in[21];
    const float* b_hh_l1r = (const float*)d_in[22];
    const float* mlp_w1   = (const float*)d_in[23];
    const float* mlp_b1   = (const float*)d_in[24];
    const float* mlp_w2   = (const float*)d_in[25];
    const float* mlp_b2   = (const float*)d_in[26];
    float* out = (float*)d_out;

    // addresses of device scratch
    float *px, *pg0, *pg1, *phv0, *phv1, *pa, *pb;
    cudaGetSymbolAddress((void**)&px,   d_x);
    cudaGetSymbolAddress((void**)&pg0,  d_g0);
    cudaGetSymbolAddress((void**)&pg1,  d_g1);
    cudaGetSymbolAddress((void**)&phv0, d_hv0);
    cudaGetSymbolAddress((void**)&phv1, d_hv1);
    cudaGetSymbolAddress((void**)&pa,   d_pa);
    cudaGetSymbolAddress((void**)&pb,   d_pb);

    dim3 gg(NG / 64, SEQ / 64, 2);   // (25, 5, 2)

    // 1. embeddings
    embed_kernel<<<(SEQ * INDIM + 255) / 256, 256>>>(words, tags, wemb, temb);

    // 2. layer-0 input projections fwd+bwd in one launch (biases folded in)
    gemm_tn2<<<gg, 256>>>(px, INDIM, w_ih_l0, w_ih_l0r, INDIM,
                          b_ih_l0, b_hh_l0, b_ih_l0r, b_hh_l0r,
                          pg0, pg1, INDIM);

    // 3. layer-0 bilstm (persistent, 134 blocks)
    lstm_phase<<<2 * GSZ, 256>>>(w_hh_l0, w_hh_l0r, h0, c0, 0, pg0, pg1, phv0);

    // 4. layer-1 input projections fwd+bwd
    gemm_tn2<<<gg, 256>>>(phv0, BI2, w_ih_l1, w_ih_l1r, BI2,
                          b_ih_l1, b_hh_l1, b_ih_l1r, b_hh_l1r,
                          pg0, pg1, BI2);

    // 5. layer-1 bilstm
    lstm_phase<<<2 * GSZ, 256>>>(w_hh_l1, w_hh_l1r, h0, c0, 2, pg0, pg1, phv1);

    // 6. MLP split projections: a = hv@w1a^T + b1 ; b = hv@w1b^T  (one launch)
    gemm_tn2<<<gg, 256>>>(phv1, BI2, mlp_w1, mlp_w1 + BI2, NG,
                          mlp_b1, nullptr, nullptr, nullptr,
                          pa, pb, BI2);

    // 7. output borders + pairwise scores
    init_out<<<2, 256>>>(out);
    pairwise_kernel<<<dim3(10, 10), 256>>>(pa, pb, mlp_w2, mlp_b2, out);
}

// round 8
// speedup vs baseline: 1.9357x; 1.9357x over previous
#include <cuda_runtime.h>

// ---------------- problem constants ----------------
#define SEQ   320
#define HH    400          // hidden size H
#define NG    1600         // 4*H gate width
#define BI2   800          // 2*H bilstm output width
#define WDIM  300
#define TDIM  100
#define INDIM 400

// LSTM distribution: 67 blocks per direction, 6 hidden units each (last block 4)
#define GSZ   67
#define KB    6

// ---------------- device scratch (no allocations allowed) ----------------
__device__ float d_x[SEQ * INDIM];        // embedded input
__device__ float d_g0[SEQ * NG];          // precomputed x@W_ih^T + biases (fwd)
__device__ float d_g1[SEQ * NG];          // (bwd)
__device__ float d_hv0[SEQ * BI2];        // layer-0 bilstm output
__device__ float d_hv1[SEQ * BI2];        // layer-1 bilstm output
__device__ float d_pa[SEQ * NG];          // a = hv@w1a^T + b1
__device__ float d_pb[SEQ * NG];          // b = hv@w1b^T
__device__ float d_hbuf[2][2][HH];        // [dir][parity][H] recurrent h exchange
// one flag per producer block, PADDED to a private 128B L2 line (slot [..][0]).
// This is the fix for the R7 regression: unpadded flags packed ~32 flags/line,
// so ~4300 spinners hammered 1-2 LTS slices and starved the publish stores.
__device__ int   d_hflag[2][GSZ][32];
__device__ int   d_done;                  // end-of-kernel reset barrier

// ---------------- math helpers ----------------
__device__ __forceinline__ float sigm_f(float x) {
    float e = __expf(-x);
    return 1.0f / (1.0f + e);
}
__device__ __forceinline__ float tanh_f(float x) {
    float e = __expf(2.0f * x);
    return 1.0f - 2.0f / (e + 1.0f);   // exact limits at +-inf
}

// ---------------- embedding concat ----------------
__global__ void embed_kernel(const int* __restrict__ words, const int* __restrict__ tags,
                             const float* __restrict__ wemb, const float* __restrict__ temb) {
    int idx = blockIdx.x * blockDim.x + threadIdx.x;
    if (idx >= SEQ * INDIM) return;
    int t = idx / INDIM, d = idx % INDIM;
    d_x[idx] = (d < WDIM) ? wemb[words[t] * WDIM + d]
                          : temb[tags[t] * TDIM + (d - WDIM)];
}

// ---------------- dual GEMM: z=0/1 select B/bias/C; C[M,N] = A*B^T + b0 + b1 ----
__global__ void __launch_bounds__(256) gemm_tn2(
    const float* __restrict__ A, int lda,
    const float* __restrict__ B0, const float* __restrict__ B1, int ldb,
    const float* __restrict__ b00, const float* __restrict__ b01,
    const float* __restrict__ b10, const float* __restrict__ b11,
    float* __restrict__ C0, float* __restrict__ C1, int K)
{
    const float* B     = blockIdx.z ? B1  : B0;
    const float* bias0 = blockIdx.z ? b10 : b00;
    const float* bias1 = blockIdx.z ? b11 : b01;
    float*       C     = blockIdx.z ? C1  : C0;

    __shared__ float As[16][68];
    __shared__ float Bs[16][68];
    int tid = threadIdx.x;
    int bm = blockIdx.y * 64, bn = blockIdx.x * 64;
    int row = tid >> 2, kq = tid & 3;      // loaders
    int ty  = tid >> 4, tx = tid & 15;     // compute 4x4 each
    float acc[4][4] = {};

    for (int k0 = 0; k0 < K; k0 += 16) {
        __syncthreads();
        float4 av = *(const float4*)&A[(bm + row) * lda + k0 + kq * 4];
        float4 bv = *(const float4*)&B[(bn + row) * ldb + k0 + kq * 4];
        As[kq*4+0][row] = av.x; As[kq*4+1][row] = av.y;
        As[kq*4+2][row] = av.z; As[kq*4+3][row] = av.w;
        Bs[kq*4+0][row] = bv.x; Bs[kq*4+1][row] = bv.y;
        Bs[kq*4+2][row] = bv.z; Bs[kq*4+3][row] = bv.w;
        __syncthreads();
        #pragma unroll
        for (int kk = 0; kk < 16; kk++) {
            float4 a4 = *(const float4*)&As[kk][ty * 4];
            float4 b4 = *(const float4*)&Bs[kk][tx * 4];
            float aa[4] = {a4.x, a4.y, a4.z, a4.w};
            float bb[4] = {b4.x, b4.y, b4.z, b4.w};
            #pragma unroll
            for (int i = 0; i < 4; i++)
                #pragma unroll
                for (int j = 0; j < 4; j++)
                    acc[i][j] += aa[i] * bb[j];
        }
    }
    #pragma unroll
    for (int i = 0; i < 4; i++) {
        int m = bm + ty * 4 + i;
        #pragma unroll
        for (int j = 0; j < 4; j++) {
            int n = bn + tx * 4 + j;
            float v = acc[i][j];
            if (bias0) v += bias0[n];
            if (bias1) v += bias1[n];
            C[m * NG + n] = v;
        }
    }
}

// ---------------- persistent bidirectional LSTM phase ----------------
// grid = 2*GSZ blocks, 256 threads. blocks [0,GSZ): forward, [GSZ,2*GSZ): backward.
// Each block owns KB hidden units: its 4*KB W_hh rows stay resident in smem.
// Per-step sync: producer publishes a per-block flag on its OWN 128B line
// (fence + STG); consumer thread i polls flag i — 67 parallel polls, each to
// a distinct L2 line. No per-step atomics, no slice hotspot.
__global__ void __launch_bounds__(256, 1) lstm_phase(
    const float* __restrict__ whh_f, const float* __restrict__ whh_b,
    const float* __restrict__ h0, const float* __restrict__ c0, int h0base,
    const float* __restrict__ gpre_f, const float* __restrict__ gpre_b,
    float* __restrict__ hv_out)
{
    __shared__ float Ws[4 * KB][HH];     // 38.4 KB
    __shared__ float h_s[HH];
    __shared__ float g_s[4 * KB];
    __shared__ float gp_s[4 * KB];
    __shared__ float c_s[KB];
    __shared__ int   last_s;

    const int tid  = threadIdx.x;
    const int dir  = (blockIdx.x >= GSZ) ? 1 : 0;
    const int slot = dir ? (blockIdx.x - GSZ) : blockIdx.x;
    const int k0   = slot * KB;
    const int kn   = min(KB, HH - k0);   // last block covers 4
    const float* whh  = dir ? whh_b  : whh_f;
    const float* gpre = dir ? gpre_b : gpre_f;
    const int h0row = h0base + dir;

    // preload W_hh slice: smem row r = gate*KB + kk  <->  W_hh row gate*HH + k0 + kk
    for (int idx = tid; idx < 4 * KB * HH; idx += blockDim.x) {
        int r = idx / HH, m = idx - r * HH;
        int g = r / KB, kk = r - g * KB;
        Ws[r][m] = (kk < kn) ? whh[(g * HH + k0 + kk) * HH + m] : 0.0f;
    }
    if (tid < KB) c_s[tid] = (tid < kn) ? c0[h0row * HH + k0 + tid] : 0.0f;
    if (tid == 0) last_s = 0;
    __syncthreads();

    const int wid = tid >> 5, lane = tid & 31;
    volatile int* myflag = &d_hflag[dir][slot][0];
    volatile int* pollfl = (tid < GSZ) ? &d_hflag[dir][tid][0] : 0;

    for (int s = 0; s < SEQ; s++) {
        const int t = dir ? (SEQ - 1 - s) : s;   // physical time index

        // prefetch this step's precomputed gate inputs (independent of h)
        if (tid < 4 * KB) {
            int g = tid / KB, kk = tid - g * KB;
            gp_s[tid] = (kk < kn) ? __ldg(&gpre[t * NG + g * HH + k0 + kk]) : 0.0f;
        }
        // wait: all blocks of this direction must have published h(s-1).
        // each poll thread spins on its own 128B line.
        if (s > 0 && tid < GSZ) {
            while (*pollfl < s) { }
        }
        __syncthreads();

        // load h (L2-coherent, bypass L1)
        if (s == 0) {
            for (int m = tid; m < HH; m += blockDim.x) h_s[m] = h0[h0row * HH + m];
        } else {
            const float* hsrc = d_hbuf[dir][s & 1];
            for (int m = tid; m < HH; m += blockDim.x) h_s[m] = __ldcg(&hsrc[m]);
        }
        __syncthreads();

        // 24 dot products of length 400; warp w handles rows w, w+8, w+16
        {
            const float* w0  = Ws[wid];
            const float* w1  = Ws[wid + 8];
            const float* w2p = Ws[wid + 16];
            float s0 = 0.f, s1 = 0.f, s2 = 0.f;
            #pragma unroll
            for (int u = 0; u < 12; u++) {
                int m = lane + u * 32;
                float hv = h_s[m];
                s0 += w0[m] * hv; s1 += w1[m] * hv; s2 += w2p[m] * hv;
            }
            {   // tail: elements 384..399 (lanes 0..15)
                int m = lane + 384;
                if (m < HH) {
                    float hv = h_s[m];
                    s0 += w0[m] * hv; s1 += w1[m] * hv; s2 += w2p[m] * hv;
                }
            }
            #pragma unroll
            for (int off = 16; off; off >>= 1) {
                s0 += __shfl_xor_sync(0xffffffffu, s0, off);
                s1 += __shfl_xor_sync(0xffffffffu, s1, off);
                s2 += __shfl_xor_sync(0xffffffffu, s2, off);
            }
            if (lane == 0) {
                g_s[wid]      = s0 + gp_s[wid];
                g_s[wid + 8]  = s1 + gp_s[wid + 8];
                g_s[wid + 16] = s2 + gp_s[wid + 16];
            }
        }
        __syncthreads();

        // gate nonlinearities + state update (warp 0 only: tid < kn <= 6)
        float hval = 0.0f;
        if (tid < kn) {
            float gi = g_s[0 * KB + tid];
            float gf = g_s[1 * KB + tid];
            float gg = g_s[2 * KB + tid];
            float go = g_s[3 * KB + tid];
            float i = sigm_f(gi), f = sigm_f(gf), o = sigm_f(go);
            float c = f * c_s[tid] + i * tanh_f(gg);
            c_s[tid] = c;
            hval = o * tanh_f(c);
            d_hbuf[dir][(s + 1) & 1][k0 + tid] = hval;
        }
        // publish FIRST (critical path), archive hv_out after
        __syncwarp();
        if (tid == 0 && s < SEQ - 1) {
            __threadfence();
            *myflag = s + 1;
        }
        if (tid < kn) {
            hv_out[t * BI2 + dir * HH + k0 + tid] = hval;
        }
        // warps 1..7 proceed; they re-converge at the next __syncthreads
    }

    // end-of-kernel barrier: last block to arrive resets all flags for replay
    __syncthreads();
    if (tid == 0) {
        __threadfence();
        int v = atomicAdd(&d_done, 1) + 1;
        last_s = (v == 2 * GSZ);
    }
    __syncthreads();
    if (last_s) {
        int* fl = (int*)d_hflag;
        for (int i = tid; i < 2 * GSZ * 32; i += blockDim.x) fl[i] = 0;
        __syncthreads();
        if (tid == 0) { __threadfence(); d_done = 0; }
    }
}

// ---------------- output border init ----------------
__global__ void init_out(float* __restrict__ out) {
    int i = blockIdx.x * blockDim.x + threadIdx.x;
    if (i <= SEQ) {
        out[i]       = (i == 0) ? 1.0f : 0.0f;   // row 0
        out[i * 321] = (i == 0) ? 1.0f : 0.0f;   // col 0
    }
}

// ---------------- pairwise biaffine-style scores ----------------
// out[1+i][1+j] = (i==j) ? 0 : sum_k relu(a[i,k]+b[j,k])*w2[k] + b2
__global__ void __launch_bounds__(256) pairwise_kernel(
    const float* __restrict__ A, const float* __restrict__ Bm,
    const float* __restrict__ w2, const float* __restrict__ b2,
    float* __restrict__ out)
{
    __shared__ float As[32][34], Bs[32][34], w2s[32];
    int tid = threadIdx.x;
    int bi = blockIdx.y * 32, bj = blockIdx.x * 32;
    int ty = tid >> 4, tx = tid & 15;
    int row = tid >> 3, kq = tid & 7;
    float a00 = 0.f, a01 = 0.f, a10 = 0.f, a11 = 0.f;

    for (int k0 = 0; k0 < NG; k0 += 32) {
        __syncthreads();
        float4 av = *(const float4*)&A [(bi + row) * NG + k0 + kq * 4];
        float4 bv = *(const float4*)&Bm[(bj + row) * NG + k0 + kq * 4];
        As[kq*4+0][row] = av.x; As[kq*4+1][row] = av.y;
        As[kq*4+2][row] = av.z; As[kq*4+3][row] = av.w;
        Bs[kq*4+0][row] = bv.x; Bs[kq*4+1][row] = bv.y;
        Bs[kq*4+2][row] = bv.z; Bs[kq*4+3][row] = bv.w;
        if (tid < 32) w2s[tid] = w2[k0 + tid];
        __syncthreads();
        #pragma unroll
        for (int kk = 0; kk < 32; kk++) {
            float w = w2s[kk];
            float2 a = *(const float2*)&As[kk][ty * 2];
            float2 b = *(const float2*)&Bs[kk][tx * 2];
            a00 += fmaxf(a.x + b.x, 0.f) * w;
            a01 += fmaxf(a.x + b.y, 0.f) * w;
            a10 += fmaxf(a.y + b.x, 0.f) * w;
            a11 += fmaxf(a.y + b.y, 0.f) * w;
        }
    }
    float bb = b2[0];
    int gi = bi + ty * 2, gj = bj + tx * 2;
    out[(gi + 1) * 321 + (gj + 1)] = (gi     == gj    ) ? 0.f : a00 + bb;
    out[(gi + 1) * 321 + (gj + 2)] = (gi     == gj + 1) ? 0.f : a01 + bb;
    out[(gi + 2) * 321 + (gj + 1)] = (gi + 1 == gj    ) ? 0.f : a10 + bb;
    out[(gi + 2) * 321 + (gj + 2)] = (gi     == gj    ) ? 0.f : a11 + bb;
}

// ---------------- host orchestration ----------------
extern "C" void kernel_launch(void* const* d_in, const int* in_sizes, int n_in,
                              void* d_out, int out_size) {
    const int*   words    = (const int*)  d_in[0];
    const int*   tags     = (const int*)  d_in[1];
    const float* wemb     = (const float*)d_in[3];
    const float* temb     = (const float*)d_in[4];
    const float* h0       = (const float*)d_in[5];
    const float* c0       = (const float*)d_in[6];
    const float* w_ih_l0  = (const float*)d_in[7];
    const float* w_hh_l0  = (const float*)d_in[8];
    const float* b_ih_l0  = (const float*)d_in[9];
    const float* b_hh_l0  = (const float*)d_in[10];
    const float* w_ih_l0r = (const float*)d_in[11];
    const float* w_hh_l0r = (const float*)d_in[12];
    const float* b_ih_l0r = (const float*)d_in[13];
    const float* b_hh_l0r = (const float*)d_in[14];
    const float* w_ih_l1  = (const float*)d_in[15];
    const float* w_hh_l1  = (const float*)d_in[16];
    const float* b_ih_l1  = (const float*)d_in[17];
    const float* b_hh_l1  = (const float*)d_in[18];
    const float* w_ih_l1r = (const float*)d_in[19];
    const float* w_hh_l1r = (const float*)d_in[20];
    const float* b_ih_l1r = (const float*)d_in[21];
    const float* b_hh_l1r = (const float*)d_in[22];
    const float* mlp_w1   = (const float*)d_in[23];
    const float* mlp_b1   = (const float*)d_in[24];
    const float* mlp_w2   = (const float*)d_in[25];
    const float* mlp_b2   = (const float*)d_in[26];
    float* out = (float*)d_out;

    // addresses of device scratch
    float *px, *pg0, *pg1, *phv0, *phv1, *pa, *pb;
    cudaGetSymbolAddress((void**)&px,   d_x);
    cudaGetSymbolAddress((void**)&pg0,  d_g0);
    cudaGetSymbolAddress((void**)&pg1,  d_g1);
    cudaGetSymbolAddress((void**)&phv0, d_hv0);
    cudaGetSymbolAddress((void**)&phv1, d_hv1);
    cudaGetSymbolAddress((void**)&pa,   d_pa);
    cudaGetSymbolAddress((void**)&pb,   d_pb);

    dim3 gg(NG / 64, SEQ / 64, 2);   // (25, 5, 2)

    // 1. embeddings
    embed_kernel<<<(SEQ * INDIM + 255) / 256, 256>>>(words, tags, wemb, temb);

    // 2. layer-0 input projections fwd+bwd in one launch (biases folded in)
    gemm_tn2<<<gg, 256>>>(px, INDIM, w_ih_l0, w_ih_l0r, INDIM,
                          b_ih_l0, b_hh_l0, b_ih_l0r, b_hh_l0r,
                          pg0, pg1, INDIM);

    // 3. layer-0 bilstm (persistent, 134 blocks)
    lstm_phase<<<2 * GSZ, 256>>>(w_hh_l0, w_hh_l0r, h0, c0, 0, pg0, pg1, phv0);

    // 4. layer-1 input projections fwd+bwd
    gemm_tn2<<<gg, 256>>>(phv0, BI2, w_ih_l1, w_ih_l1r, BI2,
                          b_ih_l1, b_hh_l1, b_ih_l1r, b_hh_l1r,
                          pg0, pg1, BI2);

    // 5. layer-1 bilstm
    lstm_phase<<<2 * GSZ, 256>>>(w_hh_l1, w_hh_l1r, h0, c0, 2, pg0, pg1, phv1);

    // 6. MLP split projections: a = hv@w1a^T + b1 ; b = hv@w1b^T  (one launch)
    gemm_tn2<<<gg, 256>>>(phv1, BI2, mlp_w1, mlp_w1 + BI2, NG,
                          mlp_b1, nullptr, nullptr, nullptr,
                          pa, pb, BI2);

    // 7. output borders + pairwise scores
    init_out<<<2, 256>>>(out);
    pairwise_kernel<<<dim3(10, 10), 256>>>(pa, pb, mlp_w2, mlp_b2, out);
}